// round 4
// baseline (speedup 1.0000x reference)
#include <cuda_runtime.h>
#include <cstdint>
#include <cstddef>

#define NDIM 8192
#define CDIM 16
#define KSEL 131072u
#define MAXDEG 64
#define CAP 512
#define BUF_CAP 33554432u   // 2^25 >= N(N-1)/2 -> full fallback always fits
#define LOOP_BLOCKS 148

static constexpr size_t NN = (size_t)NDIM * (size_t)NDIM;
static constexpr size_t NSLOTS = (size_t)NDIM * (size_t)CAP;

// ---------------- device scratch ----------------
__device__ unsigned long long g_buf[BUF_CAP];
__device__ unsigned int  g_bufCnt;
__device__ unsigned char g_labels8[NDIM];
__device__ double        g_sameMass, g_totMass;
__device__ float         g_wsame, g_wdiff;
__device__ int           g_skip;
__device__ int           g_needFallback;
__device__ unsigned int  g_hist1[4096];
__device__ unsigned int  g_hist2[4096];
__device__ unsigned int  g_hist3[256];
__device__ unsigned int  g_bA, g_bAB;
__device__ unsigned int  g_thrBits;
__device__ unsigned int  g_cntGtA, g_cntGtB;
__device__ unsigned int  g_needEq;
__device__ int           g_nbr[NSLOTS];
__device__ float         g_pf[NSLOTS];
__device__ float         g_pr[NSLOTS];
__device__ unsigned char g_act[NSLOTS];
__device__ int           g_deg[NDIM];
__device__ unsigned int  g_thrU[NDIM];
__device__ unsigned char g_keepall[NDIM];
__device__ unsigned int  g_eqIdx[KSEL];
__device__ unsigned int  g_eqCnt;
__device__ unsigned int  g_changedArr[12];
__device__ unsigned int  g_tk[4];
__device__ unsigned int  g_barCount, g_barGen;

// ---------------- grid barrier (148 co-resident blocks) ----------------
__device__ __forceinline__ void gridBar() {
    __syncthreads();
    if (threadIdx.x == 0) {
        unsigned gen = atomicAdd(&g_barGen, 0u);
        __threadfence();
        if (atomicAdd(&g_barCount, 1u) == LOOP_BLOCKS - 1) {
            g_barCount = 0u;
            __threadfence();
            atomicAdd(&g_barGen, 1u);
        } else {
            unsigned spins = 0;
            while (atomicAdd(&g_barGen, 0u) == gen) {
                if (++spins > (1u << 28)) break;
                __nanosleep(64);
            }
        }
    }
    __syncthreads();
}

// Block-parallel boundary-bin search (256 threads). cumGe(b)=base+sum_{b'>=b}h[b'].
__device__ void scanSelect4096(const unsigned* hist, unsigned baseCum,
                               unsigned* outBin, unsigned* outCntGt) {
    __shared__ unsigned part[256];
    int t = threadIdx.x;
    unsigned local[16];
    unsigned s = 0;
#pragma unroll
    for (int k = 0; k < 16; k++) { local[k] = __ldcg(&hist[t * 16 + k]); s += local[k]; }
    part[t] = s;
    __syncthreads();
    for (int off = 1; off < 256; off <<= 1) {
        unsigned v = (t + off < 256) ? part[t + off] : 0u;
        __syncthreads();
        part[t] += v;
        __syncthreads();
    }
    unsigned cum = baseCum + ((t < 255) ? part[t + 1] : 0u);
#pragma unroll
    for (int k = 15; k >= 0; k--) {
        unsigned h = local[k];
        unsigned cg = cum + h;
        if (cg >= KSEL && cum < KSEL) { *outBin = (unsigned)(t * 16 + k); *outCntGt = cum; }
        cum = cg;
    }
}

__device__ void scanSelect256(const unsigned* hist, unsigned baseCum, unsigned prefix12) {
    __shared__ unsigned part2[256];
    int t = threadIdx.x;
    unsigned h = __ldcg(&hist[t]);
    part2[t] = h;
    __syncthreads();
    for (int off = 1; off < 256; off <<= 1) {
        unsigned v = (t + off < 256) ? part2[t + off] : 0u;
        __syncthreads();
        part2[t] += v;
        __syncthreads();
    }
    unsigned cum = baseCum + ((t < 255) ? part2[t + 1] : 0u);
    unsigned cg = cum + h;
    if (cg >= KSEL && cum < KSEL) {
        g_thrBits = (prefix12 << 8) | (unsigned)t;
        g_needEq = KSEL - cum;
    }
}

// ---------------- init: clear (block 32) + argmax (blocks 0..31) ----------------
__global__ void initK(const float* __restrict__ lp) {
    int t = threadIdx.x;
    if (blockIdx.x == 32) {
        for (int k = t; k < 4096; k += 256) { g_hist1[k] = 0; g_hist2[k] = 0; }
        if (t < 256) g_hist3[t] = 0;
        for (int k = t; k < NDIM; k += 256) g_deg[k] = 0;
        if (t < 12) g_changedArr[t] = 0;
        if (t < 4)  g_tk[t] = 0;
        if (t == 0) {
            g_bufCnt = 0; g_eqCnt = 0; g_needFallback = 0;
            g_sameMass = 0.0; g_totMass = 0.0;
            g_needEq = 0; g_thrBits = 0xFFFFFFFFu;
        }
        return;
    }
    int i = blockIdx.x * 256 + t;
    float best = lp[(size_t)i * CDIM];
    int bi = 0;
#pragma unroll
    for (int c = 1; c < CDIM; c++) {
        float v = lp[(size_t)i * CDIM + c];
        if (v > best) { best = v; bi = c; }
    }
    g_labels8[i] = (unsigned char)bi;
}

// ---------------- mass pass: 4 rows/block; decide folded into last block ----------------
__global__ void massK(const float* __restrict__ adj) {
    __shared__ unsigned char slab[NDIM];
    __shared__ double ssh[256], sth[256];
    int t = threadIdx.x;
    int i0 = blockIdx.x * 4;
    for (int k = t; k < NDIM / 4; k += 256)
        ((unsigned*)slab)[k] = ((const unsigned*)g_labels8)[k];
    __syncthreads();
    float fs = 0.f, ft = 0.f;
#pragma unroll
    for (int r = 0; r < 4; r++) {
        int i = i0 + r;
        unsigned li4 = (unsigned)slab[i] * 0x01010101u;
        const float4* row = (const float4*)(adj + (size_t)i * NDIM);
        for (int q = t; q < NDIM / 4; q += 256) {
            float4 a = __ldcs(&row[q]);
            unsigned l4 = ((unsigned*)slab)[q];
            unsigned eq = __vcmpeq4(l4, li4);
            int j0 = q * 4;
            if (i >= j0 && i < j0 + 4) eq &= ~(0xFFu << ((i - j0) * 8));
            ft += a.x + a.y + a.z + a.w;
            if (eq & 0x000000FFu) fs += a.x;
            if (eq & 0x0000FF00u) fs += a.y;
            if (eq & 0x00FF0000u) fs += a.z;
            if (eq & 0xFF000000u) fs += a.w;
        }
    }
    ssh[t] = (double)fs; sth[t] = (double)ft;
    __syncthreads();
    for (int off = 128; off > 0; off >>= 1) {
        if (t < off) { ssh[t] += ssh[t + off]; sth[t] += sth[t + off]; }
        __syncthreads();
    }
    if (t == 0) {
        atomicAdd(&g_sameMass, ssh[0]);
        atomicAdd(&g_totMass, sth[0]);
        __threadfence();
        if (atomicAdd(&g_tk[0], 1u) == gridDim.x - 1) {
            double sm = g_sameMass, tm = g_totMass;
            double dm = tm - sm;
            float cur = (float)(sm / tm);
            g_wsame = fminf(fmaxf(0.7f / (cur + 1e-6f), (float)(1.0 / 3.0)), 3.0f);
            g_wdiff = fminf(fmaxf(0.3f / (1.0f - cur + 1e-6f), (float)(1.0 / 3.0)), 3.0f);
            g_skip = (sm <= 1e-6 || dm <= 1e-6 || fabsf(cur - 0.7f) <= 0.05f) ? 1 : 0;
        }
    }
}

// ---------------- P compute + candidate append + level-1 hist ----------------
template <bool FB>
__global__ void pmatK(const float* __restrict__ adj) {
    __shared__ float sAt[64][65];
    __shared__ unsigned char slj[64];
    __shared__ unsigned short sMask[64][4];
    __shared__ unsigned shH[4096];
    __shared__ unsigned warpTot[8], warpBase[8];
    __shared__ unsigned blockBase;
    int t = threadIdx.x;
    int bi = blockIdx.y, bj = blockIdx.x;
    bool doWork = (bj >= bi) && (!FB || g_needFallback);

    if (doWork) {
        const bool isDiag = (bi == bj);
        for (int k = t; k < 4096; k += 256) shH[k] = 0;
        if (t < 64) slj[t] = g_labels8[bj * 64 + t];
        for (int e = t; e < 64 * 16; e += 256) {
            int r2 = e >> 4, c4 = (e & 15) * 4;
            float4 v = __ldcs((const float4*)(adj + (size_t)(bj * 64 + r2) * NDIM + bi * 64 + c4));
            sAt[r2][c4] = v.x; sAt[r2][c4 + 1] = v.y; sAt[r2][c4 + 2] = v.z; sAt[r2][c4 + 3] = v.w;
        }
        __syncthreads();
        {   // per-row 64-bit label match masks, 16 bits per thread
            int r = t >> 2, q = t & 3;
            unsigned char lr = g_labels8[bi * 64 + r];
            unsigned short m = 0;
#pragma unroll
            for (int cc = 0; cc < 16; cc++)
                m |= (unsigned short)((lr == slj[q * 16 + cc]) ? 1 : 0) << cc;
            sMask[r][q] = m;
        }
        __syncthreads();
        int skip = g_skip;
        float ws = g_wsame, wd = g_wdiff;
        unsigned pivot = skip ? 0x3F000000u : 0x3F800000u;
        unsigned lo = FB ? 0u : pivot;
        unsigned hi = FB ? pivot : 0xFFFFFFFFu;
        unsigned long long loc[16];
        int cnt = 0;
        for (int e = t; e < 64 * 16; e += 256) {
            int r = e >> 4, c4 = (e & 15) * 4;
            int i = bi * 64 + r;
            int j0 = bj * 64 + c4;
            float4 a = __ldcs((const float4*)(adj + (size_t)i * NDIM + j0));
            float av[4] = {a.x, a.y, a.z, a.w};
            unsigned nib = ((unsigned)sMask[r][c4 >> 4] >> (c4 & 15)) & 0xFu;
#pragma unroll
            for (int k = 0; k < 4; k++) {
                int j = j0 + k;
                if (isDiag && j <= i) continue;
                float p;
                if (skip) p = av[k];
                else {
                    float w = ((nib >> k) & 1u) ? ws : wd;
                    p = 0.5f * __fadd_rn(__fmul_rn(av[k], w), __fmul_rn(sAt[c4 + k][r], w));
                }
                unsigned bits = __float_as_uint(p);
                if (bits >= lo && bits < hi) {
                    loc[cnt++] = ((unsigned long long)bits << 32) | (unsigned)(i * NDIM + j);
                    atomicAdd(&shH[bits >> 20], 1u);
                }
            }
        }
        // block-aggregated buffer append
        unsigned pre = (unsigned)cnt;
        for (int d = 1; d < 32; d <<= 1) {
            unsigned v = __shfl_up_sync(0xFFFFFFFFu, pre, d);
            if ((t & 31) >= d) pre += v;
        }
        if ((t & 31) == 31) warpTot[t >> 5] = pre;
        __syncthreads();
        if (t == 0) {
            unsigned s = 0;
            for (int w = 0; w < 8; w++) { unsigned v = warpTot[w]; warpBase[w] = s; s += v; }
            blockBase = s ? atomicAdd(&g_bufCnt, s) : 0u;
        }
        __syncthreads();
        unsigned base = blockBase + warpBase[t >> 5] + (pre - (unsigned)cnt);
        for (int k = 0; k < cnt; k++) {
            unsigned pos = base + (unsigned)k;
            if (pos < BUF_CAP) g_buf[pos] = loc[k];
        }
        for (int k = t; k < 4096; k += 256)
            if (shH[k]) atomicAdd(&g_hist1[k], shH[k]);
    }
    if (!FB) {
        __syncthreads();
        if (t == 0) {
            __threadfence();
            if (atomicAdd(&g_tk[1], 1u) == gridDim.x * gridDim.y - 1)
                g_needFallback = (g_bufCnt < KSEL) ? 1 : 0;
        }
    }
}

// ---------------- edge emission ----------------
__device__ __forceinline__ void emitEdge(int i, int j, float p,
                                         const float* __restrict__ adj, int skip) {
    float pf_i, pr_i, pf_j, pr_j;
    if (skip) {
        float aij = adj[(size_t)i * NDIM + j];
        float aji = adj[(size_t)j * NDIM + i];
        pf_i = aij; pr_i = aji; pf_j = aji; pr_j = aij;
    } else {
        pf_i = pr_i = pf_j = pr_j = p;
    }
    int di = atomicAdd(&g_deg[i], 1);
    if (di < CAP) {
        size_t s = (size_t)i * CAP + di;
        g_nbr[s] = j; g_pf[s] = pf_i; g_pr[s] = pr_i; g_act[s] = 1;
    }
    int dj = atomicAdd(&g_deg[j], 1);
    if (dj < CAP) {
        size_t s = (size_t)j * CAP + dj;
        g_nbr[s] = i; g_pf[s] = pf_j; g_pr[s] = pr_j; g_act[s] = 1;
    }
}

// ---------------- persistent tail: scans, hists, select, ties, prune loop ----------------
__global__ void __launch_bounds__(256, 1) postK(const float* __restrict__ adj) {
    __shared__ unsigned shH[4096];
    int t = threadIdx.x;
    unsigned n = min(__ldcg(&g_bufCnt), BUF_CAP);

    // phase 0: scanA (block 0)
    if (blockIdx.x == 0) scanSelect4096(g_hist1, 0u, &g_bA, &g_cntGtA);
    gridBar();

    // phase 1: histB
    {
        for (int k = t; k < 4096; k += 256) shH[k] = 0;
        __syncthreads();
        unsigned bA = __ldcg(&g_bA);
        for (unsigned idx = blockIdx.x * 256u + t; idx < n; idx += LOOP_BLOCKS * 256u) {
            unsigned bits = (unsigned)(__ldcg(&g_buf[idx]) >> 32);
            if ((bits >> 20) == bA) atomicAdd(&shH[(bits >> 8) & 0xFFFu], 1u);
        }
        __syncthreads();
        for (int k = t; k < 4096; k += 256)
            if (shH[k]) atomicAdd(&g_hist2[k], shH[k]);
    }
    gridBar();

    // phase 2: scanB (block 0)
    if (blockIdx.x == 0) {
        __shared__ unsigned binOut;
        scanSelect4096(g_hist2, g_cntGtA, &binOut, &g_cntGtB);
        __syncthreads();
        if (t == 0) g_bAB = (__ldcg(&g_bA) << 12) | binOut;
    }
    gridBar();

    // phase 3: histC
    {
        if (t < 256) shH[t] = 0;
        __syncthreads();
        unsigned bAB = __ldcg(&g_bAB);
        for (unsigned idx = blockIdx.x * 256u + t; idx < n; idx += LOOP_BLOCKS * 256u) {
            unsigned bits = (unsigned)(__ldcg(&g_buf[idx]) >> 32);
            if ((bits >> 8) == bAB) atomicAdd(&shH[bits & 0xFFu], 1u);
        }
        __syncthreads();
        if (shH[t]) atomicAdd(&g_hist3[t], shH[t]);
    }
    gridBar();

    // phase 4: scanC (block 0)
    if (blockIdx.x == 0) scanSelect256(g_hist3, __ldcg(&g_cntGtB), __ldcg(&g_bAB));
    gridBar();

    // phase 5: select + emit
    {
        unsigned thr = __ldcg(&g_thrBits);
        int skip = g_skip;
        for (unsigned idx = blockIdx.x * 256u + t; idx < n; idx += LOOP_BLOCKS * 256u) {
            unsigned long long e = __ldcg(&g_buf[idx]);
            unsigned bits = (unsigned)(e >> 32);
            if (bits > thr) {
                unsigned fi = (unsigned)e;
                emitEdge((int)(fi >> 13), (int)(fi & 8191u), __uint_as_float(bits), adj, skip);
            } else if (bits == thr) {
                unsigned pos = atomicAdd(&g_eqCnt, 1u);
                if (pos < KSEL) g_eqIdx[pos] = (unsigned)e;
            }
        }
    }
    gridBar();

    // phase 6: tie resolution (lowest flat index wins)
    {
        unsigned M = min((unsigned)atomicAdd(&g_eqCnt, 0u), KSEL);
        unsigned need = __ldcg(&g_needEq);
        unsigned thr = __ldcg(&g_thrBits);
        int skip = g_skip;
        if (need > 0) {
            for (unsigned u = blockIdx.x * 256u + t; u < M; u += LOOP_BLOCKS * 256u) {
                unsigned idx = __ldcg(&g_eqIdx[u]);
                unsigned rank = 0;
                for (unsigned s = 0; s < M; s++) rank += (__ldcg(&g_eqIdx[s]) < idx) ? 1u : 0u;
                if (rank < need)
                    emitEdge((int)(idx >> 13), (int)(idx & 8191u), __uint_as_float(thr), adj, skip);
            }
        }
    }
    gridBar();

    // phase 7: degree-cap prune loop (warp per row; early exit on fixed point)
    int lane = t & 31;
    int warpG = blockIdx.x * 8 + (t >> 5);
    const int nW = LOOP_BLOCKS * 8;
    __shared__ unsigned sCont;

    for (int iter = 0; iter < 10; iter++) {
        for (int i = warpG; i < NDIM; i += nW) {
            size_t base = (size_t)i * CAP;
            int degE = min(__ldcg(&g_deg[i]), CAP);
            float v[16]; unsigned am = 0, dc = 0;
#pragma unroll
            for (int k = 0; k < 16; k++) {
                int s = lane + k * 32;
                bool a = (s < degE) && (__ldcg(&g_act[base + s]) != 0);
                if (a) { v[k] = __ldcg(&g_pf[base + s]); am |= 1u << k; dc++; }
            }
            unsigned deg = __reduce_add_sync(0xFFFFFFFFu, dc);
            if (deg <= (unsigned)MAXDEG) {
                if (lane == 0) __stcg(&g_keepall[i], (unsigned char)1);
                continue;
            }
            if (lane == 0) __stcg(&g_keepall[i], (unsigned char)0);
            unsigned T = 0;
            for (int b = 31; b >= 0; b--) {
                unsigned cand = T | (1u << b);
                unsigned c = 0;
#pragma unroll
                for (int k = 0; k < 16; k++)
                    if (((am >> k) & 1u) && __float_as_uint(v[k]) >= cand) c++;
                c = __reduce_add_sync(0xFFFFFFFFu, c);
                if (c >= (unsigned)MAXDEG) T = cand;
            }
            if (lane == 0) __stcg(&g_thrU[i], T);
        }
        gridBar();
        bool removed = false;
        for (int i = warpG; i < NDIM; i += nW) {
            size_t base = (size_t)i * CAP;
            int degE = min(__ldcg(&g_deg[i]), CAP);
            unsigned kaI = __ldcg(&g_keepall[i]);
            unsigned thrI = __ldcg(&g_thrU[i]);
            for (int s = lane; s < degE; s += 32) {
                if (!__ldcg(&g_act[base + s])) continue;
                int j = __ldcg(&g_nbr[base + s]);
                bool ki = kaI || (__float_as_uint(__ldcg(&g_pf[base + s])) >= thrI);
                bool kj = __ldcg(&g_keepall[j]) ||
                          (__float_as_uint(__ldcg(&g_pr[base + s])) >= __ldcg(&g_thrU[j]));
                if (!(ki && kj)) { __stcg(&g_act[base + s], (unsigned char)0); removed = true; }
            }
        }
        if (__any_sync(0xFFFFFFFFu, removed) && lane == 0)
            atomicOr(&g_changedArr[iter + 1], 1u);
        gridBar();
        if (t == 0) sCont = atomicAdd(&g_changedArr[iter + 1], 0u);
        __syncthreads();
        if (!sCont) break;
    }
}

// ---------------- fused zero + scatter output ----------------
__global__ void outK(float* __restrict__ out) {
    __shared__ unsigned sBits[256];
    int i = blockIdx.x, t = threadIdx.x;
    sBits[t] = 0;
    __syncthreads();
    size_t base = (size_t)i * CAP;
    int degE = min(g_deg[i], CAP);
    for (int s = t; s < degE; s += 256)
        if (g_act[base + s]) {
            int j = g_nbr[base + s];
            atomicOr(&sBits[j >> 5], 1u << (j & 31));
        }
    __syncthreads();
    float4* orow = (float4*)(out + (size_t)i * NDIM);
    for (int q = t; q < NDIM / 4; q += 256) {
        unsigned w = sBits[q >> 3];
        unsigned sh = (q & 7) * 4;
        float4 v;
        v.x = (w >> sh & 1u) ? 1.f : 0.f;
        v.y = (w >> (sh + 1) & 1u) ? 1.f : 0.f;
        v.z = (w >> (sh + 2) & 1u) ? 1.f : 0.f;
        v.w = (w >> (sh + 3) & 1u) ? 1.f : 0.f;
        __stcs(&orow[q], v);
    }
}

// ---------------- launch ----------------
extern "C" void kernel_launch(void* const* d_in, const int* in_sizes, int n_in,
                              void* d_out, int out_size) {
    const float* adj = (const float*)d_in[0];
    const float* lp  = (const float*)d_in[1];
    float* out = (float*)d_out;

    initK<<<33, 256>>>(lp);                    // clear + argmax fused
    massK<<<NDIM / 4, 256>>>(adj);             // + decide (last block)
    {
        dim3 grid(128, 128);
        pmatK<false><<<grid, 256>>>(adj);      // + fallback flag (last block)
        pmatK<true><<<grid, 256>>>(adj);       // fallback (usually no-op)
    }
    postK<<<LOOP_BLOCKS, 256>>>(adj);          // scans + hists + select + ties + prune
    outK<<<NDIM, 256>>>(out);
}

// round 5
// speedup vs baseline: 1.0172x; 1.0172x over previous
#include <cuda_runtime.h>
#include <cstdint>
#include <cstddef>

#define NDIM 8192
#define CDIM 16
#define KSEL 131072u
#define MAXDEG 64
#define CAP 512
#define BUF_CAP 33554432u   // 2^25 >= N(N-1)/2 -> full fallback always fits
#define LOOP_BLOCKS 148

static constexpr size_t NN = (size_t)NDIM * (size_t)NDIM;
static constexpr size_t NSLOTS = (size_t)NDIM * (size_t)CAP;

// ---------------- device scratch ----------------
__device__ unsigned long long g_buf[BUF_CAP];
__device__ unsigned int  g_bufCnt;
__device__ unsigned char g_labels8[NDIM];
__device__ double        g_sameMass, g_totMass;
__device__ float         g_wsame, g_wdiff;
__device__ int           g_skip;
__device__ unsigned int  g_hist1[4096];
__device__ unsigned int  g_hist2[4096];
__device__ unsigned int  g_hist3[256];
__device__ unsigned int  g_bA, g_bAB;
__device__ unsigned int  g_thrBits;
__device__ unsigned int  g_cntGtA, g_cntGtB;
__device__ unsigned int  g_needEq;
__device__ int           g_nbr[NSLOTS];
__device__ float         g_pf[NSLOTS];
__device__ float         g_pr[NSLOTS];
__device__ unsigned char g_act[NSLOTS];
__device__ int           g_deg[NDIM];
__device__ unsigned int  g_thrU[NDIM];
__device__ unsigned char g_keepall[NDIM];
__device__ unsigned int  g_eqIdx[KSEL];
__device__ unsigned int  g_eqCnt;
__device__ unsigned int  g_changedArr[12];
__device__ unsigned int  g_tk[4];
__device__ unsigned int  g_barCount, g_barGen;

// ---------------- grid barrier (148 co-resident blocks) ----------------
__device__ __forceinline__ void gridBar() {
    __threadfence();
    __syncthreads();
    if (threadIdx.x == 0) {
        unsigned gen = atomicAdd(&g_barGen, 0u);
        if (atomicAdd(&g_barCount, 1u) == LOOP_BLOCKS - 1) {
            g_barCount = 0u;
            __threadfence();
            atomicAdd(&g_barGen, 1u);
        } else {
            unsigned spins = 0;
            while (atomicAdd(&g_barGen, 0u) == gen) {
                if (++spins > (1u << 28)) break;
                __nanosleep(64);
            }
        }
    }
    __syncthreads();
}

// Boundary-bin search over 4096 bins, 1024 threads. cumGe(b)=base+sum_{b'>=b}h[b'].
__device__ void scanSelect4096(const unsigned* hist, unsigned baseCum,
                               unsigned* outBin, unsigned* outCntGt) {
    __shared__ unsigned part[1024];
    int t = threadIdx.x;
    unsigned local[4];
    unsigned s = 0;
#pragma unroll
    for (int k = 0; k < 4; k++) { local[k] = __ldcg(&hist[t * 4 + k]); s += local[k]; }
    part[t] = s;
    __syncthreads();
    for (int off = 1; off < 1024; off <<= 1) {
        unsigned v = (t + off < 1024) ? part[t + off] : 0u;
        __syncthreads();
        part[t] += v;
        __syncthreads();
    }
    unsigned cum = baseCum + ((t < 1023) ? part[t + 1] : 0u);
#pragma unroll
    for (int k = 3; k >= 0; k--) {
        unsigned h = local[k];
        unsigned cg = cum + h;
        if (cg >= KSEL && cum < KSEL) { *outBin = (unsigned)(t * 4 + k); *outCntGt = cum; }
        cum = cg;
    }
}

__device__ void scanSelect256(const unsigned* hist, unsigned baseCum, unsigned prefix12) {
    __shared__ unsigned part2[1024];
    int t = threadIdx.x;
    unsigned h = (t < 256) ? __ldcg(&hist[t]) : 0u;
    part2[t] = h;
    __syncthreads();
    for (int off = 1; off < 1024; off <<= 1) {
        unsigned v = (t + off < 1024) ? part2[t + off] : 0u;
        __syncthreads();
        part2[t] += v;
        __syncthreads();
    }
    unsigned cum = baseCum + ((t < 1023) ? part2[t + 1] : 0u);
    unsigned cg = cum + h;
    if (t < 256 && cg >= KSEL && cum < KSEL) {
        g_thrBits = (prefix12 << 8) | (unsigned)t;
        g_needEq = KSEL - cum;
    }
}

// ---------------- init: clear (block 32) + argmax (blocks 0..31) ----------------
__global__ void initK(const float* __restrict__ lp) {
    int t = threadIdx.x;
    if (blockIdx.x == 32) {
        for (int k = t; k < 4096; k += 256) { g_hist1[k] = 0; g_hist2[k] = 0; }
        if (t < 256) g_hist3[t] = 0;
        for (int k = t; k < NDIM; k += 256) g_deg[k] = 0;
        if (t < 12) g_changedArr[t] = 0;
        if (t < 4)  g_tk[t] = 0;
        if (t == 0) {
            g_bufCnt = 0; g_eqCnt = 0;
            g_sameMass = 0.0; g_totMass = 0.0;
            g_needEq = 0; g_thrBits = 0xFFFFFFFFu;
        }
        return;
    }
    int i = blockIdx.x * 256 + t;
    float best = lp[(size_t)i * CDIM];
    int bi = 0;
#pragma unroll
    for (int c = 1; c < CDIM; c++) {
        float v = lp[(size_t)i * CDIM + c];
        if (v > best) { best = v; bi = c; }
    }
    g_labels8[i] = (unsigned char)bi;
}

// ---------------- mass pass (R3 form: 1 row/block); decide in last block ----------------
__global__ void massK(const float* __restrict__ adj) {
    __shared__ unsigned char slab[NDIM];
    __shared__ double ssh[256], sth[256];
    int i = blockIdx.x, t = threadIdx.x;
    for (int k = t; k < NDIM / 4; k += 256)
        ((unsigned*)slab)[k] = ((const unsigned*)g_labels8)[k];
    __syncthreads();
    unsigned li4 = (unsigned)slab[i] * 0x01010101u;
    const float4* row = (const float4*)(adj + (size_t)i * NDIM);
    float fs = 0.f, ft = 0.f;
    for (int q = t; q < NDIM / 4; q += 256) {
        float4 a = __ldcs(&row[q]);
        unsigned l4 = ((unsigned*)slab)[q];
        unsigned eq = __vcmpeq4(l4, li4);
        int j0 = q * 4;
        if (i >= j0 && i < j0 + 4) eq &= ~(0xFFu << ((i - j0) * 8));
        ft += a.x + a.y + a.z + a.w;
        if (eq & 0x000000FFu) fs += a.x;
        if (eq & 0x0000FF00u) fs += a.y;
        if (eq & 0x00FF0000u) fs += a.z;
        if (eq & 0xFF000000u) fs += a.w;
    }
    ssh[t] = (double)fs; sth[t] = (double)ft;
    __syncthreads();
    for (int off = 128; off > 0; off >>= 1) {
        if (t < off) { ssh[t] += ssh[t + off]; sth[t] += sth[t + off]; }
        __syncthreads();
    }
    if (t == 0) {
        atomicAdd(&g_sameMass, ssh[0]);
        atomicAdd(&g_totMass, sth[0]);
        __threadfence();
        if (atomicAdd(&g_tk[0], 1u) == gridDim.x - 1) {
            double sm = g_sameMass, tm = g_totMass;
            double dm = tm - sm;
            float cur = (float)(sm / tm);
            g_wsame = fminf(fmaxf(0.7f / (cur + 1e-6f), (float)(1.0 / 3.0)), 3.0f);
            g_wdiff = fminf(fmaxf(0.3f / (1.0f - cur + 1e-6f), (float)(1.0 / 3.0)), 3.0f);
            g_skip = (sm <= 1e-6 || dm <= 1e-6 || fabsf(cur - 0.7f) <= 0.05f) ? 1 : 0;
        }
    }
}

__device__ __forceinline__ unsigned pivotBits(int skip) {
    return skip ? 0x3F666666u : 0x40000000u;   // 0.9f : 2.0f
}

// ---------------- P compute + candidate append (no hist, no fallback grid) ----------------
__global__ void pmatK(const float* __restrict__ adj) {
    int bi = blockIdx.y, bj = blockIdx.x;
    if (bj < bi) return;
    __shared__ float sAt[64][65];
    __shared__ unsigned char slj[64];
    __shared__ unsigned short sMask[64][4];
    __shared__ unsigned warpTot[8], warpBase[8];
    __shared__ unsigned blockBase;
    int t = threadIdx.x;
    const bool isDiag = (bi == bj);

    if (t < 64) slj[t] = g_labels8[bj * 64 + t];
    for (int e = t; e < 64 * 16; e += 256) {
        int r2 = e >> 4, c4 = (e & 15) * 4;
        float4 v = __ldcs((const float4*)(adj + (size_t)(bj * 64 + r2) * NDIM + bi * 64 + c4));
        sAt[r2][c4] = v.x; sAt[r2][c4 + 1] = v.y; sAt[r2][c4 + 2] = v.z; sAt[r2][c4 + 3] = v.w;
    }
    __syncthreads();
    {   // per-row label match masks, 16 bits per thread
        int r = t >> 2, q = t & 3;
        unsigned char lr = g_labels8[bi * 64 + r];
        unsigned short m = 0;
#pragma unroll
        for (int cc = 0; cc < 16; cc++)
            m |= (unsigned short)((lr == slj[q * 16 + cc]) ? 1 : 0) << cc;
        sMask[r][q] = m;
    }
    __syncthreads();
    int skip = g_skip;
    float ws = g_wsame, wd = g_wdiff;
    unsigned lo = pivotBits(skip);
    unsigned long long loc[16];
    int cnt = 0;
    for (int e = t; e < 64 * 16; e += 256) {
        int r = e >> 4, c4 = (e & 15) * 4;
        int i = bi * 64 + r;
        int j0 = bj * 64 + c4;
        float4 a = __ldcs((const float4*)(adj + (size_t)i * NDIM + j0));
        float av[4] = {a.x, a.y, a.z, a.w};
        unsigned nib = ((unsigned)sMask[r][c4 >> 4] >> (c4 & 15)) & 0xFu;
#pragma unroll
        for (int k = 0; k < 4; k++) {
            int j = j0 + k;
            if (isDiag && j <= i) continue;
            float p;
            if (skip) p = av[k];
            else {
                float w = ((nib >> k) & 1u) ? ws : wd;
                p = 0.5f * __fadd_rn(__fmul_rn(av[k], w), __fmul_rn(sAt[c4 + k][r], w));
            }
            unsigned bits = __float_as_uint(p);
            if (bits >= lo)
                loc[cnt++] = ((unsigned long long)bits << 32) | (unsigned)(i * NDIM + j);
        }
    }
    // block-aggregated buffer append
    unsigned pre = (unsigned)cnt;
    for (int d = 1; d < 32; d <<= 1) {
        unsigned v = __shfl_up_sync(0xFFFFFFFFu, pre, d);
        if ((t & 31) >= d) pre += v;
    }
    if ((t & 31) == 31) warpTot[t >> 5] = pre;
    __syncthreads();
    if (t == 0) {
        unsigned s = 0;
        for (int w = 0; w < 8; w++) { unsigned v = warpTot[w]; warpBase[w] = s; s += v; }
        blockBase = s ? atomicAdd(&g_bufCnt, s) : 0u;
    }
    __syncthreads();
    unsigned base = blockBase + warpBase[t >> 5] + (pre - (unsigned)cnt);
    for (int k = 0; k < cnt; k++) {
        unsigned pos = base + (unsigned)k;
        if (pos < BUF_CAP) g_buf[pos] = loc[k];
    }
}

// ---------------- edge emission ----------------
__device__ __forceinline__ void emitEdge(int i, int j, float p,
                                         const float* __restrict__ adj, int skip) {
    float pf_i, pr_i, pf_j, pr_j;
    if (skip) {
        float aij = adj[(size_t)i * NDIM + j];
        float aji = adj[(size_t)j * NDIM + i];
        pf_i = aij; pr_i = aji; pf_j = aji; pr_j = aij;
    } else {
        pf_i = pr_i = pf_j = pr_j = p;
    }
    int di = atomicAdd(&g_deg[i], 1);
    if (di < CAP) {
        size_t s = (size_t)i * CAP + di;
        g_nbr[s] = j; g_pf[s] = pf_i; g_pr[s] = pr_i; g_act[s] = 1;
    }
    int dj = atomicAdd(&g_deg[j], 1);
    if (dj < CAP) {
        size_t s = (size_t)j * CAP + dj;
        g_nbr[s] = i; g_pf[s] = pf_j; g_pr[s] = pr_j; g_act[s] = 1;
    }
}

// ---------------- persistent tail ----------------
__global__ void __launch_bounds__(1024, 1) postK(const float* __restrict__ adj) {
    __shared__ unsigned shH[4096];
    int t = threadIdx.x;

    // phase F: rare-path fallback — if pivot under-collected, append everything below it
    if (__ldcg(&g_bufCnt) < KSEL) {
        int skip = g_skip;
        float ws = g_wsame, wd = g_wdiff;
        unsigned lo = pivotBits(skip);
        for (int tile = blockIdx.x; tile < 128 * 128; tile += LOOP_BLOCKS) {
            int bi = tile >> 7, bj = tile & 127;
            if (bj < bi) continue;
            for (int e = t; e < 4096; e += 1024) {
                int i = bi * 64 + (e >> 6), j = bj * 64 + (e & 63);
                if (j <= i) continue;
                float a1 = adj[(size_t)i * NDIM + j];
                float p;
                if (skip) p = a1;
                else {
                    float a2 = adj[(size_t)j * NDIM + i];
                    float w = (g_labels8[i] == g_labels8[j]) ? ws : wd;
                    p = 0.5f * __fadd_rn(__fmul_rn(a1, w), __fmul_rn(a2, w));
                }
                unsigned bits = __float_as_uint(p);
                if (bits < lo) {
                    unsigned pos = atomicAdd(&g_bufCnt, 1u);
                    if (pos < BUF_CAP)
                        g_buf[pos] = ((unsigned long long)bits << 32) | (unsigned)(i * NDIM + j);
                }
            }
        }
    }
    gridBar();
    unsigned n = min(__ldcg(&g_bufCnt), BUF_CAP);

    // phase H1: build hist1 from buffer
    {
        for (int k = t; k < 4096; k += 1024) shH[k] = 0;
        __syncthreads();
        for (unsigned idx = blockIdx.x * 1024u + t; idx < n; idx += LOOP_BLOCKS * 1024u)
            atomicAdd(&shH[(unsigned)(__ldcg(&g_buf[idx]) >> 32) >> 20], 1u);
        __syncthreads();
        for (int k = t; k < 4096; k += 1024)
            if (shH[k]) atomicAdd(&g_hist1[k], shH[k]);
    }
    gridBar();
    if (blockIdx.x == 0) scanSelect4096(g_hist1, 0u, &g_bA, &g_cntGtA);
    gridBar();

    // phase H2
    {
        for (int k = t; k < 4096; k += 1024) shH[k] = 0;
        __syncthreads();
        unsigned bA = __ldcg(&g_bA);
        for (unsigned idx = blockIdx.x * 1024u + t; idx < n; idx += LOOP_BLOCKS * 1024u) {
            unsigned bits = (unsigned)(__ldcg(&g_buf[idx]) >> 32);
            if ((bits >> 20) == bA) atomicAdd(&shH[(bits >> 8) & 0xFFFu], 1u);
        }
        __syncthreads();
        for (int k = t; k < 4096; k += 1024)
            if (shH[k]) atomicAdd(&g_hist2[k], shH[k]);
    }
    gridBar();
    if (blockIdx.x == 0) {
        __shared__ unsigned binOut;
        scanSelect4096(g_hist2, __ldcg(&g_cntGtA), &binOut, &g_cntGtB);
        __syncthreads();
        if (t == 0) g_bAB = (__ldcg(&g_bA) << 12) | binOut;
    }
    gridBar();

    // phase H3
    {
        if (t < 256) shH[t] = 0;
        __syncthreads();
        unsigned bAB = __ldcg(&g_bAB);
        for (unsigned idx = blockIdx.x * 1024u + t; idx < n; idx += LOOP_BLOCKS * 1024u) {
            unsigned bits = (unsigned)(__ldcg(&g_buf[idx]) >> 32);
            if ((bits >> 8) == bAB) atomicAdd(&shH[bits & 0xFFu], 1u);
        }
        __syncthreads();
        if (t < 256 && shH[t]) atomicAdd(&g_hist3[t], shH[t]);
    }
    gridBar();
    if (blockIdx.x == 0) scanSelect256(g_hist3, __ldcg(&g_cntGtB), __ldcg(&g_bAB));
    gridBar();

    // phase S: select + emit
    {
        unsigned thr = __ldcg(&g_thrBits);
        int skip = g_skip;
        for (unsigned idx = blockIdx.x * 1024u + t; idx < n; idx += LOOP_BLOCKS * 1024u) {
            unsigned long long e = __ldcg(&g_buf[idx]);
            unsigned bits = (unsigned)(e >> 32);
            if (bits > thr) {
                unsigned fi = (unsigned)e;
                emitEdge((int)(fi >> 13), (int)(fi & 8191u), __uint_as_float(bits), adj, skip);
            } else if (bits == thr) {
                unsigned pos = atomicAdd(&g_eqCnt, 1u);
                if (pos < KSEL) g_eqIdx[pos] = (unsigned)e;
            }
        }
    }
    gridBar();

    // phase T: tie resolution (lowest flat index wins)
    {
        unsigned M = min((unsigned)atomicAdd(&g_eqCnt, 0u), KSEL);
        unsigned need = __ldcg(&g_needEq);
        unsigned thr = __ldcg(&g_thrBits);
        int skip = g_skip;
        if (need > 0) {
            for (unsigned u = blockIdx.x * 1024u + t; u < M; u += LOOP_BLOCKS * 1024u) {
                unsigned idx = __ldcg(&g_eqIdx[u]);
                unsigned rank = 0;
                for (unsigned s = 0; s < M; s++) rank += (__ldcg(&g_eqIdx[s]) < idx) ? 1u : 0u;
                if (rank < need)
                    emitEdge((int)(idx >> 13), (int)(idx & 8191u), __uint_as_float(thr), adj, skip);
            }
        }
    }
    gridBar();

    // phase P: degree-cap prune loop, warp per row, early exit on fixed point
    int lane = t & 31;
    int warpG = blockIdx.x * 32 + (t >> 5);
    const int nW = LOOP_BLOCKS * 32;
    __shared__ unsigned sCont;

    for (int iter = 0; iter < 10; iter++) {
        for (int i = warpG; i < NDIM; i += nW) {
            size_t base = (size_t)i * CAP;
            int degE = min(__ldcg(&g_deg[i]), CAP);
            float v[16]; unsigned am = 0, dc = 0;
#pragma unroll
            for (int k = 0; k < 16; k++) {
                int s = lane + k * 32;
                bool a = (s < degE) && (__ldcg(&g_act[base + s]) != 0);
                if (a) { v[k] = __ldcg(&g_pf[base + s]); am |= 1u << k; dc++; }
            }
            unsigned deg = __reduce_add_sync(0xFFFFFFFFu, dc);
            if (deg <= (unsigned)MAXDEG) {
                if (lane == 0) __stcg(&g_keepall[i], (unsigned char)1);
                continue;
            }
            if (lane == 0) __stcg(&g_keepall[i], (unsigned char)0);
            unsigned T = 0;
            for (int b = 31; b >= 0; b--) {
                unsigned cand = T | (1u << b);
                unsigned c = 0;
#pragma unroll
                for (int k = 0; k < 16; k++)
                    if (((am >> k) & 1u) && __float_as_uint(v[k]) >= cand) c++;
                c = __reduce_add_sync(0xFFFFFFFFu, c);
                if (c >= (unsigned)MAXDEG) T = cand;
            }
            if (lane == 0) __stcg(&g_thrU[i], T);
        }
        gridBar();
        bool removed = false;
        for (int i = warpG; i < NDIM; i += nW) {
            size_t base = (size_t)i * CAP;
            int degE = min(__ldcg(&g_deg[i]), CAP);
            unsigned kaI = __ldcg(&g_keepall[i]);
            unsigned thrI = __ldcg(&g_thrU[i]);
            for (int s = lane; s < degE; s += 32) {
                if (!__ldcg(&g_act[base + s])) continue;
                int j = __ldcg(&g_nbr[base + s]);
                bool ki = kaI || (__float_as_uint(__ldcg(&g_pf[base + s])) >= thrI);
                bool kj = __ldcg(&g_keepall[j]) ||
                          (__float_as_uint(__ldcg(&g_pr[base + s])) >= __ldcg(&g_thrU[j]));
                if (!(ki && kj)) { __stcg(&g_act[base + s], (unsigned char)0); removed = true; }
            }
        }
        if (__any_sync(0xFFFFFFFFu, removed) && lane == 0)
            atomicOr(&g_changedArr[iter + 1], 1u);
        gridBar();
        if (t == 0) sCont = atomicAdd(&g_changedArr[iter + 1], 0u);
        __syncthreads();
        if (!sCont) break;
    }
}

// ---------------- fused zero + scatter output ----------------
__global__ void outK(float* __restrict__ out) {
    __shared__ unsigned sBits[256];
    int i = blockIdx.x, t = threadIdx.x;
    sBits[t] = 0;
    __syncthreads();
    size_t base = (size_t)i * CAP;
    int degE = min(g_deg[i], CAP);
    for (int s = t; s < degE; s += 256)
        if (g_act[base + s]) {
            int j = g_nbr[base + s];
            atomicOr(&sBits[j >> 5], 1u << (j & 31));
        }
    __syncthreads();
    float4* orow = (float4*)(out + (size_t)i * NDIM);
    for (int q = t; q < NDIM / 4; q += 256) {
        unsigned w = sBits[q >> 3];
        unsigned sh = (q & 7) * 4;
        float4 v;
        v.x = (w >> sh & 1u) ? 1.f : 0.f;
        v.y = (w >> (sh + 1) & 1u) ? 1.f : 0.f;
        v.z = (w >> (sh + 2) & 1u) ? 1.f : 0.f;
        v.w = (w >> (sh + 3) & 1u) ? 1.f : 0.f;
        __stcs(&orow[q], v);
    }
}

// ---------------- launch ----------------
extern "C" void kernel_launch(void* const* d_in, const int* in_sizes, int n_in,
                              void* d_out, int out_size) {
    const float* adj = (const float*)d_in[0];
    const float* lp  = (const float*)d_in[1];
    float* out = (float*)d_out;

    initK<<<33, 256>>>(lp);                    // clear + argmax fused
    massK<<<NDIM, 256>>>(adj);                 // + decide (last block)
    {
        dim3 grid(128, 128);
        pmatK<<<grid, 256>>>(adj);             // candidates only (no hist)
    }
    postK<<<LOOP_BLOCKS, 1024>>>(adj);         // fallback + scans + select + ties + prune
    outK<<<NDIM, 256>>>(out);
}

// round 6
// speedup vs baseline: 1.4026x; 1.3788x over previous
#include <cuda_runtime.h>
#include <cstdint>
#include <cstddef>

#define NDIM 8192
#define CDIM 16
#define KSEL 131072u
#define MAXDEG 64
#define CAP 512
#define BUF_CAP 33554432u   // 2^25 >= N(N-1)/2 -> full fallback always fits
#define LOOP_BLOCKS 148

static constexpr size_t NN = (size_t)NDIM * (size_t)NDIM;
static constexpr size_t NSLOTS = (size_t)NDIM * (size_t)CAP;

// ---------------- device scratch ----------------
__device__ unsigned long long g_buf[BUF_CAP];
__device__ unsigned int  g_bufCnt;
__device__ unsigned char g_labels8[NDIM];
__device__ double        g_sameMass, g_totMass;
__device__ float         g_wsame, g_wdiff;
__device__ int           g_skip;
__device__ unsigned int  g_hist1[4096];
__device__ unsigned int  g_hist2[4096];
__device__ unsigned int  g_hist3[256];
__device__ int           g_nbr[NSLOTS];
__device__ float         g_pf[NSLOTS];
__device__ float         g_pr[NSLOTS];
__device__ unsigned char g_act[NSLOTS];
__device__ int           g_deg[NDIM];
__device__ unsigned int  g_thrU[NDIM];
__device__ unsigned char g_keepall[NDIM];
__device__ unsigned int  g_eqIdx[KSEL];
__device__ unsigned int  g_eqCnt;
__device__ unsigned int  g_changedArr[12];
__device__ unsigned int  g_tk[4];
__device__ unsigned int  g_barCount, g_barGen;

// ---------------- grid barrier (148 co-resident blocks) ----------------
__device__ __forceinline__ void gridBar() {
    __threadfence();
    __syncthreads();
    if (threadIdx.x == 0) {
        unsigned gen = atomicAdd(&g_barGen, 0u);
        if (atomicAdd(&g_barCount, 1u) == LOOP_BLOCKS - 1) {
            g_barCount = 0u;
            __threadfence();
            atomicAdd(&g_barGen, 1u);
        } else {
            unsigned spins = 0;
            while (atomicAdd(&g_barGen, 0u) == gen) {
                if (++spins > (1u << 28)) break;
                __nanosleep(64);
            }
        }
    }
    __syncthreads();
}

// Boundary-bin search over 4096 bins, 1024 threads, results into SHARED outputs.
// All blocks run this redundantly on identical global data -> no grid barrier needed
// between scan and the next phase. cumGe(b)=base+sum_{b'>=b}h[b'].
__device__ void scanSelect4096(const unsigned* hist, unsigned baseCum,
                               unsigned* outBin, unsigned* outCntGt) {
    __shared__ unsigned part[1024];
    int t = threadIdx.x;
    unsigned local[4];
    unsigned s = 0;
#pragma unroll
    for (int k = 0; k < 4; k++) { local[k] = __ldcg(&hist[t * 4 + k]); s += local[k]; }
    part[t] = s;
    __syncthreads();
    for (int off = 1; off < 1024; off <<= 1) {
        unsigned v = (t + off < 1024) ? part[t + off] : 0u;
        __syncthreads();
        part[t] += v;
        __syncthreads();
    }
    unsigned cum = baseCum + ((t < 1023) ? part[t + 1] : 0u);
#pragma unroll
    for (int k = 3; k >= 0; k--) {
        unsigned h = local[k];
        unsigned cg = cum + h;
        if (cg >= KSEL && cum < KSEL) { *outBin = (unsigned)(t * 4 + k); *outCntGt = cum; }
        cum = cg;
    }
    __syncthreads();
}

__device__ void scanSelect256(const unsigned* hist, unsigned baseCum, unsigned prefix12,
                              unsigned* outThr, unsigned* outNeed) {
    __shared__ unsigned part2[1024];
    int t = threadIdx.x;
    unsigned h = (t < 256) ? __ldcg(&hist[t]) : 0u;
    part2[t] = h;
    __syncthreads();
    for (int off = 1; off < 1024; off <<= 1) {
        unsigned v = (t + off < 1024) ? part2[t + off] : 0u;
        __syncthreads();
        part2[t] += v;
        __syncthreads();
    }
    unsigned cum = baseCum + ((t < 1023) ? part2[t + 1] : 0u);
    unsigned cg = cum + h;
    if (t < 256 && cg >= KSEL && cum < KSEL) {
        *outThr = (prefix12 << 8) | (unsigned)t;
        *outNeed = KSEL - cum;
    }
    __syncthreads();
}

// ---------------- init: clear (block 32) + argmax (blocks 0..31) ----------------
__global__ void initK(const float* __restrict__ lp) {
    int t = threadIdx.x;
    if (blockIdx.x == 32) {
        for (int k = t; k < 4096; k += 256) { g_hist1[k] = 0; g_hist2[k] = 0; }
        if (t < 256) g_hist3[t] = 0;
        for (int k = t; k < NDIM; k += 256) g_deg[k] = 0;
        if (t < 12) g_changedArr[t] = 0;
        if (t < 4)  g_tk[t] = 0;
        if (t == 0) {
            g_bufCnt = 0; g_eqCnt = 0;
            g_sameMass = 0.0; g_totMass = 0.0;
        }
        return;
    }
    int i = blockIdx.x * 256 + t;
    float best = lp[(size_t)i * CDIM];
    int bi = 0;
#pragma unroll
    for (int c = 1; c < CDIM; c++) {
        float v = lp[(size_t)i * CDIM + c];
        if (v > best) { best = v; bi = c; }
    }
    g_labels8[i] = (unsigned char)bi;
}

// ---------------- mass pass; decide in last block ----------------
__global__ void massK(const float* __restrict__ adj) {
    __shared__ unsigned char slab[NDIM];
    __shared__ double ssh[256], sth[256];
    int i = blockIdx.x, t = threadIdx.x;
    for (int k = t; k < NDIM / 4; k += 256)
        ((unsigned*)slab)[k] = ((const unsigned*)g_labels8)[k];
    __syncthreads();
    unsigned li4 = (unsigned)slab[i] * 0x01010101u;
    const float4* row = (const float4*)(adj + (size_t)i * NDIM);
    float fs = 0.f, ft = 0.f;
    for (int q = t; q < NDIM / 4; q += 256) {
        float4 a = __ldcs(&row[q]);
        unsigned l4 = ((unsigned*)slab)[q];
        unsigned eq = __vcmpeq4(l4, li4);
        int j0 = q * 4;
        if (i >= j0 && i < j0 + 4) eq &= ~(0xFFu << ((i - j0) * 8));
        ft += a.x + a.y + a.z + a.w;
        if (eq & 0x000000FFu) fs += a.x;
        if (eq & 0x0000FF00u) fs += a.y;
        if (eq & 0x00FF0000u) fs += a.z;
        if (eq & 0xFF000000u) fs += a.w;
    }
    ssh[t] = (double)fs; sth[t] = (double)ft;
    __syncthreads();
    for (int off = 128; off > 0; off >>= 1) {
        if (t < off) { ssh[t] += ssh[t + off]; sth[t] += sth[t + off]; }
        __syncthreads();
    }
    if (t == 0) {
        atomicAdd(&g_sameMass, ssh[0]);
        atomicAdd(&g_totMass, sth[0]);
        __threadfence();
        if (atomicAdd(&g_tk[0], 1u) == gridDim.x - 1) {
            double sm = g_sameMass, tm = g_totMass;
            double dm = tm - sm;
            float cur = (float)(sm / tm);
            g_wsame = fminf(fmaxf(0.7f / (cur + 1e-6f), (float)(1.0 / 3.0)), 3.0f);
            g_wdiff = fminf(fmaxf(0.3f / (1.0f - cur + 1e-6f), (float)(1.0 / 3.0)), 3.0f);
            g_skip = (sm <= 1e-6 || dm <= 1e-6 || fabsf(cur - 0.7f) <= 0.05f) ? 1 : 0;
        }
    }
}

__device__ __forceinline__ unsigned pivotBits(int skip) {
    return skip ? 0x3F666666u : 0x40000000u;   // 0.9f : 2.0f
}

// ---------------- P compute + candidate append ----------------
__global__ void pmatK(const float* __restrict__ adj) {
    int bi = blockIdx.y, bj = blockIdx.x;
    if (bj < bi) return;
    __shared__ float sAt[64][65];
    __shared__ unsigned char slj[64];
    __shared__ unsigned short sMask[64][4];
    __shared__ unsigned warpTot[8], warpBase[8];
    __shared__ unsigned blockBase;
    int t = threadIdx.x;
    const bool isDiag = (bi == bj);

    if (t < 64) slj[t] = g_labels8[bj * 64 + t];
    for (int e = t; e < 64 * 16; e += 256) {
        int r2 = e >> 4, c4 = (e & 15) * 4;
        float4 v = __ldcs((const float4*)(adj + (size_t)(bj * 64 + r2) * NDIM + bi * 64 + c4));
        sAt[r2][c4] = v.x; sAt[r2][c4 + 1] = v.y; sAt[r2][c4 + 2] = v.z; sAt[r2][c4 + 3] = v.w;
    }
    __syncthreads();
    {
        int r = t >> 2, q = t & 3;
        unsigned char lr = g_labels8[bi * 64 + r];
        unsigned short m = 0;
#pragma unroll
        for (int cc = 0; cc < 16; cc++)
            m |= (unsigned short)((lr == slj[q * 16 + cc]) ? 1 : 0) << cc;
        sMask[r][q] = m;
    }
    __syncthreads();
    int skip = g_skip;
    float ws = g_wsame, wd = g_wdiff;
    unsigned lo = pivotBits(skip);
    unsigned long long loc[16];
    int cnt = 0;
    for (int e = t; e < 64 * 16; e += 256) {
        int r = e >> 4, c4 = (e & 15) * 4;
        int i = bi * 64 + r;
        int j0 = bj * 64 + c4;
        float4 a = __ldcs((const float4*)(adj + (size_t)i * NDIM + j0));
        float av[4] = {a.x, a.y, a.z, a.w};
        unsigned nib = ((unsigned)sMask[r][c4 >> 4] >> (c4 & 15)) & 0xFu;
#pragma unroll
        for (int k = 0; k < 4; k++) {
            int j = j0 + k;
            if (isDiag && j <= i) continue;
            float p;
            if (skip) p = av[k];
            else {
                float w = ((nib >> k) & 1u) ? ws : wd;
                p = 0.5f * __fadd_rn(__fmul_rn(av[k], w), __fmul_rn(sAt[c4 + k][r], w));
            }
            unsigned bits = __float_as_uint(p);
            if (bits >= lo)
                loc[cnt++] = ((unsigned long long)bits << 32) | (unsigned)(i * NDIM + j);
        }
    }
    unsigned pre = (unsigned)cnt;
    for (int d = 1; d < 32; d <<= 1) {
        unsigned v = __shfl_up_sync(0xFFFFFFFFu, pre, d);
        if ((t & 31) >= d) pre += v;
    }
    if ((t & 31) == 31) warpTot[t >> 5] = pre;
    __syncthreads();
    if (t == 0) {
        unsigned s = 0;
        for (int w = 0; w < 8; w++) { unsigned v = warpTot[w]; warpBase[w] = s; s += v; }
        blockBase = s ? atomicAdd(&g_bufCnt, s) : 0u;
    }
    __syncthreads();
    unsigned base = blockBase + warpBase[t >> 5] + (pre - (unsigned)cnt);
    for (int k = 0; k < cnt; k++) {
        unsigned pos = base + (unsigned)k;
        if (pos < BUF_CAP) g_buf[pos] = loc[k];
    }
}

// ---------------- edge emission ----------------
__device__ __forceinline__ void emitEdge(int i, int j, float p,
                                         const float* __restrict__ adj, int skip) {
    float pf_i, pr_i, pf_j, pr_j;
    if (skip) {
        float aij = adj[(size_t)i * NDIM + j];
        float aji = adj[(size_t)j * NDIM + i];
        pf_i = aij; pr_i = aji; pf_j = aji; pr_j = aij;
    } else {
        pf_i = pr_i = pf_j = pr_j = p;
    }
    int di = atomicAdd(&g_deg[i], 1);
    if (di < CAP) {
        size_t s = (size_t)i * CAP + di;
        g_nbr[s] = j; g_pf[s] = pf_i; g_pr[s] = pr_i; g_act[s] = 1;
    }
    int dj = atomicAdd(&g_deg[j], 1);
    if (dj < CAP) {
        size_t s = (size_t)j * CAP + dj;
        g_nbr[s] = i; g_pf[s] = pf_j; g_pr[s] = pr_j; g_act[s] = 1;
    }
}

// ---------------- persistent tail ----------------
__global__ void __launch_bounds__(1024, 1) postK(const float* __restrict__ adj) {
    __shared__ unsigned shH[4096];
    __shared__ unsigned sBA, sCntA, sBinB, sCntB, sBAB, sThr, sNeed;
    int t = threadIdx.x;
    if (t == 0) { sThr = 0xFFFFFFFFu; sNeed = 0u; }

    // phase F: rare-path fallback — if pivot under-collected, append everything below it
    if (__ldcg(&g_bufCnt) < KSEL) {
        int skip = g_skip;
        float ws = g_wsame, wd = g_wdiff;
        unsigned lo = pivotBits(skip);
        for (int tile = blockIdx.x; tile < 128 * 128; tile += LOOP_BLOCKS) {
            int bi = tile >> 7, bj = tile & 127;
            if (bj < bi) continue;
            for (int e = t; e < 4096; e += 1024) {
                int i = bi * 64 + (e >> 6), j = bj * 64 + (e & 63);
                if (j <= i) continue;
                float a1 = adj[(size_t)i * NDIM + j];
                float p;
                if (skip) p = a1;
                else {
                    float a2 = adj[(size_t)j * NDIM + i];
                    float w = (g_labels8[i] == g_labels8[j]) ? ws : wd;
                    p = 0.5f * __fadd_rn(__fmul_rn(a1, w), __fmul_rn(a2, w));
                }
                unsigned bits = __float_as_uint(p);
                if (bits < lo) {
                    unsigned pos = atomicAdd(&g_bufCnt, 1u);
                    if (pos < BUF_CAP)
                        g_buf[pos] = ((unsigned long long)bits << 32) | (unsigned)(i * NDIM + j);
                }
            }
        }
    }
    gridBar();
    unsigned n = min(__ldcg(&g_bufCnt), BUF_CAP);

    // phase H1: build hist1 from buffer
    {
        for (int k = t; k < 4096; k += 1024) shH[k] = 0;
        __syncthreads();
        for (unsigned idx = blockIdx.x * 1024u + t; idx < n; idx += LOOP_BLOCKS * 1024u)
            atomicAdd(&shH[(unsigned)(__ldcg(&g_buf[idx]) >> 32) >> 20], 1u);
        __syncthreads();
        for (int k = t; k < 4096; k += 1024)
            if (shH[k]) atomicAdd(&g_hist1[k], shH[k]);
    }
    gridBar();
    scanSelect4096(g_hist1, 0u, &sBA, &sCntA);   // all blocks, result in shared

    // phase H2
    {
        for (int k = t; k < 4096; k += 1024) shH[k] = 0;
        __syncthreads();
        unsigned bA = sBA;
        for (unsigned idx = blockIdx.x * 1024u + t; idx < n; idx += LOOP_BLOCKS * 1024u) {
            unsigned bits = (unsigned)(__ldcg(&g_buf[idx]) >> 32);
            if ((bits >> 20) == bA) atomicAdd(&shH[(bits >> 8) & 0xFFFu], 1u);
        }
        __syncthreads();
        for (int k = t; k < 4096; k += 1024)
            if (shH[k]) atomicAdd(&g_hist2[k], shH[k]);
    }
    gridBar();
    scanSelect4096(g_hist2, sCntA, &sBinB, &sCntB);
    if (t == 0) sBAB = (sBA << 12) | sBinB;
    __syncthreads();

    // phase H3
    {
        if (t < 256) shH[t] = 0;
        __syncthreads();
        unsigned bAB = sBAB;
        for (unsigned idx = blockIdx.x * 1024u + t; idx < n; idx += LOOP_BLOCKS * 1024u) {
            unsigned bits = (unsigned)(__ldcg(&g_buf[idx]) >> 32);
            if ((bits >> 8) == bAB) atomicAdd(&shH[bits & 0xFFu], 1u);
        }
        __syncthreads();
        if (t < 256 && shH[t]) atomicAdd(&g_hist3[t], shH[t]);
    }
    gridBar();
    scanSelect256(g_hist3, sCntB, sBAB, &sThr, &sNeed);

    // phase S: select + emit
    {
        unsigned thr = sThr;
        int skip = g_skip;
        for (unsigned idx = blockIdx.x * 1024u + t; idx < n; idx += LOOP_BLOCKS * 1024u) {
            unsigned long long e = __ldcg(&g_buf[idx]);
            unsigned bits = (unsigned)(e >> 32);
            if (bits > thr) {
                unsigned fi = (unsigned)e;
                emitEdge((int)(fi >> 13), (int)(fi & 8191u), __uint_as_float(bits), adj, skip);
            } else if (bits == thr) {
                unsigned pos = atomicAdd(&g_eqCnt, 1u);
                if (pos < KSEL) g_eqIdx[pos] = (unsigned)e;
            }
        }
    }
    gridBar();

    // phase T: tie resolution (lowest flat index wins) — NOTE: plain load of eqCnt,
    // ordered by gridBar's threadfence. (R5's atomicAdd(...,0) here was a 151K-thread
    // single-address atomic storm = ~80us.)
    {
        unsigned M = min(__ldcg(&g_eqCnt), KSEL);
        unsigned need = sNeed;
        unsigned thr = sThr;
        int skip = g_skip;
        if (need > 0) {
            for (unsigned u = blockIdx.x * 1024u + t; u < M; u += LOOP_BLOCKS * 1024u) {
                unsigned idx = __ldcg(&g_eqIdx[u]);
                unsigned rank = 0;
                for (unsigned s = 0; s < M; s++) rank += (__ldcg(&g_eqIdx[s]) < idx) ? 1u : 0u;
                if (rank < need)
                    emitEdge((int)(idx >> 13), (int)(idx & 8191u), __uint_as_float(thr), adj, skip);
            }
        }
    }
    gridBar();

    // phase P: degree-cap prune loop, warp per row, early exit on fixed point
    int lane = t & 31;
    int warpG = blockIdx.x * 32 + (t >> 5);
    const int nW = LOOP_BLOCKS * 32;
    __shared__ unsigned sCont;

    for (int iter = 0; iter < 10; iter++) {
        for (int i = warpG; i < NDIM; i += nW) {
            size_t base = (size_t)i * CAP;
            int degE = min(__ldcg(&g_deg[i]), CAP);
            float v[16]; unsigned am = 0, dc = 0;
#pragma unroll
            for (int k = 0; k < 16; k++) {
                int s = lane + k * 32;
                bool a = (s < degE) && (__ldcg(&g_act[base + s]) != 0);
                if (a) { v[k] = __ldcg(&g_pf[base + s]); am |= 1u << k; dc++; }
            }
            unsigned deg = __reduce_add_sync(0xFFFFFFFFu, dc);
            if (deg <= (unsigned)MAXDEG) {
                if (lane == 0) __stcg(&g_keepall[i], (unsigned char)1);
                continue;
            }
            if (lane == 0) __stcg(&g_keepall[i], (unsigned char)0);
            unsigned T = 0;
            for (int b = 31; b >= 0; b--) {
                unsigned cand = T | (1u << b);
                unsigned c = 0;
#pragma unroll
                for (int k = 0; k < 16; k++)
                    if (((am >> k) & 1u) && __float_as_uint(v[k]) >= cand) c++;
                c = __reduce_add_sync(0xFFFFFFFFu, c);
                if (c >= (unsigned)MAXDEG) T = cand;
            }
            if (lane == 0) __stcg(&g_thrU[i], T);
        }
        gridBar();
        bool removed = false;
        for (int i = warpG; i < NDIM; i += nW) {
            size_t base = (size_t)i * CAP;
            int degE = min(__ldcg(&g_deg[i]), CAP);
            unsigned kaI = __ldcg(&g_keepall[i]);
            unsigned thrI = __ldcg(&g_thrU[i]);
            for (int s = lane; s < degE; s += 32) {
                if (!__ldcg(&g_act[base + s])) continue;
                int j = __ldcg(&g_nbr[base + s]);
                bool ki = kaI || (__float_as_uint(__ldcg(&g_pf[base + s])) >= thrI);
                bool kj = __ldcg(&g_keepall[j]) ||
                          (__float_as_uint(__ldcg(&g_pr[base + s])) >= __ldcg(&g_thrU[j]));
                if (!(ki && kj)) { __stcg(&g_act[base + s], (unsigned char)0); removed = true; }
            }
        }
        if (__any_sync(0xFFFFFFFFu, removed) && lane == 0)
            atomicOr(&g_changedArr[iter + 1], 1u);
        gridBar();
        if (t == 0) sCont = __ldcg(&g_changedArr[iter + 1]);
        __syncthreads();
        if (!sCont) break;
    }
}

// ---------------- fused zero + scatter output ----------------
__global__ void outK(float* __restrict__ out) {
    __shared__ unsigned sBits[256];
    int i = blockIdx.x, t = threadIdx.x;
    sBits[t] = 0;
    __syncthreads();
    size_t base = (size_t)i * CAP;
    int degE = min(g_deg[i], CAP);
    for (int s = t; s < degE; s += 256)
        if (g_act[base + s]) {
            int j = g_nbr[base + s];
            atomicOr(&sBits[j >> 5], 1u << (j & 31));
        }
    __syncthreads();
    float4* orow = (float4*)(out + (size_t)i * NDIM);
    for (int q = t; q < NDIM / 4; q += 256) {
        unsigned w = sBits[q >> 3];
        unsigned sh = (q & 7) * 4;
        float4 v;
        v.x = (w >> sh & 1u) ? 1.f : 0.f;
        v.y = (w >> (sh + 1) & 1u) ? 1.f : 0.f;
        v.z = (w >> (sh + 2) & 1u) ? 1.f : 0.f;
        v.w = (w >> (sh + 3) & 1u) ? 1.f : 0.f;
        __stcs(&orow[q], v);
    }
}

// ---------------- launch ----------------
extern "C" void kernel_launch(void* const* d_in, const int* in_sizes, int n_in,
                              void* d_out, int out_size) {
    const float* adj = (const float*)d_in[0];
    const float* lp  = (const float*)d_in[1];
    float* out = (float*)d_out;

    initK<<<33, 256>>>(lp);                    // clear + argmax fused
    massK<<<NDIM, 256>>>(adj);                 // + decide (last block)
    {
        dim3 grid(128, 128);
        pmatK<<<grid, 256>>>(adj);             // candidates only (no hist)
    }
    postK<<<LOOP_BLOCKS, 1024>>>(adj);         // fallback + scans + select + ties + prune
    outK<<<NDIM, 256>>>(out);
}